// round 1
// baseline (speedup 1.0000x reference)
#include <cuda_runtime.h>
#include <math.h>

#define TT  256
#define BB  128
#define DD  1024
#define HH  1024
#define DH  2048
#define BH  (BB*HH)

// Scratch (device globals: no allocation allowed in kernel_launch)
static __device__ float g_Z[(size_t)TT*4*BB*HH];   // input-projection precompute [T][4][B][H] (512MB)
static __device__ float g_P[2*4*BH];               // per-step recurrent GEMM partials [ksplit][4][B][H]
static __device__ float g_c[BH];                   // cell state
static __device__ float g_zero[BH];                // zero h for t=0

// ---- packed fp32x2 FMA (Blackwell): doubles FFMA throughput vs FFMA-3reg ----
__device__ __forceinline__ void fma2(unsigned long long &acc, unsigned long long a, unsigned long long b){
    asm("fma.rn.f32x2 %0, %1, %2, %0;" : "+l"(acc) : "l"(a), "l"(b));
}
__device__ __forceinline__ unsigned long long splat2(float x){
    unsigned long long r; unsigned u = __float_as_uint(x);
    asm("mov.b64 %0, {%1, %1};" : "=l"(r) : "r"(u));
    return r;
}
__device__ __forceinline__ float2 unpack2(unsigned long long v){
    unsigned lo, hi;
    asm("mov.b64 {%0, %1}, %2;" : "=r"(lo), "=r"(hi) : "l"(v));
    return make_float2(__uint_as_float(lo), __uint_as_float(hi));
}

__global__ void k_init(){
    int i = blockIdx.x*blockDim.x + threadIdx.x;   // grid covers exactly BH
    g_c[i]    = 0.f;
    g_zero[i] = 0.f;
}

// ---------------------------------------------------------------------------
// Precompute: Z[t,g,b,n] = bias_g[n] + sum_d X[t,b,d] * W_g[n,d]   (d < 1024)
// M = T*B = 32768 rows (tile 128 = exactly one t), N = 1024 per gate, K = 1024.
// Tile 128x128xK16, 256 threads, 8x8 micro-tile via f32x2.
// ---------------------------------------------------------------------------
__global__ __launch_bounds__(256) void k_pre(
    const float* __restrict__ X,
    const float* __restrict__ Wf, const float* __restrict__ Wi,
    const float* __restrict__ Wu, const float* __restrict__ Wo,
    const float* __restrict__ bf, const float* __restrict__ bi,
    const float* __restrict__ bu, const float* __restrict__ bo)
{
    __shared__ float As[16][132];   // k-major, padded (132: 16B-aligned rows, 2-way max store conflict)
    __shared__ float Bs[16][132];

    const int g  = blockIdx.z;
    const float* __restrict__ W    = (g==0)?Wf:(g==1)?Wi:(g==2)?Wu:Wo;
    const float* __restrict__ bias = (g==0)?bf:(g==1)?bi:(g==2)?bu:bo;
    const int t   = blockIdx.y;           // m0 = t*128 (M-tile == batch)
    const int n0  = blockIdx.x*128;
    const int tid = threadIdx.x;
    const int tx  = tid & 15;             // n group (16 * 8 = 128)
    const int ty  = tid >> 4;             // m group (16 * 8 = 128)

    const float* __restrict__ A = X + (size_t)t*BB*DD;

    unsigned long long acc[8][4];
    #pragma unroll
    for (int i=0;i<8;i++){
        #pragma unroll
        for (int j=0;j<4;j++) acc[i][j]=0ull;
    }

    for (int kt=0; kt<1024; kt+=16){
        #pragma unroll
        for (int i=0;i<2;i++){
            int f = tid + i*256;
            int row = f>>2, kq = f&3;
            float4 v = *(const float4*)(A + (size_t)row*DD + kt + kq*4);
            As[kq*4+0][row]=v.x; As[kq*4+1][row]=v.y; As[kq*4+2][row]=v.z; As[kq*4+3][row]=v.w;
            float4 w = *(const float4*)(W + (size_t)(n0+row)*DH + kt + kq*4);
            Bs[kq*4+0][row]=w.x; Bs[kq*4+1][row]=w.y; Bs[kq*4+2][row]=w.z; Bs[kq*4+3][row]=w.w;
        }
        __syncthreads();
        #pragma unroll
        for (int k=0;k<16;k++){
            float a[8];
            *(float4*)(a)   = *(const float4*)&As[k][ty*8];
            *(float4*)(a+4) = *(const float4*)&As[k][ty*8+4];
            ulonglong2 q0 = *(const ulonglong2*)&Bs[k][tx*8];
            ulonglong2 q1 = *(const ulonglong2*)&Bs[k][tx*8+4];
            unsigned long long b[4] = {q0.x, q0.y, q1.x, q1.y};
            #pragma unroll
            for (int im=0; im<8; im++){
                unsigned long long a2 = splat2(a[im]);
                #pragma unroll
                for (int in=0; in<4; in++) fma2(acc[im][in], a2, b[in]);
            }
        }
        __syncthreads();
    }

    float bv[8];
    #pragma unroll
    for (int j=0;j<8;j++) bv[j] = bias[n0 + tx*8 + j];

    float* __restrict__ Zb = g_Z + ((size_t)(t*4+g)*BB)*HH + n0 + tx*8;
    #pragma unroll
    for (int im=0; im<8; im++){
        int b = ty*8+im;
        float o8[8];
        #pragma unroll
        for (int in=0;in<4;in++){
            float2 p = unpack2(acc[im][in]);
            o8[in*2]   = p.x + bv[in*2];
            o8[in*2+1] = p.y + bv[in*2+1];
        }
        *(float4*)(Zb + (size_t)b*HH)     = *(float4*)(o8);
        *(float4*)(Zb + (size_t)b*HH + 4) = *(float4*)(o8+4);
    }
}

// ---------------------------------------------------------------------------
// Recurrent GEMM (per step): P[s,g,b,n] = sum_{k in split s} h[b,k] * W_g[n, 1024+k]
// M=128 (whole batch in block), N-tile 64, K split in 2 halves of 512 -> 128 blocks.
// ---------------------------------------------------------------------------
__global__ __launch_bounds__(128) void k_rec(
    const float* __restrict__ Wf, const float* __restrict__ Wi,
    const float* __restrict__ Wu, const float* __restrict__ Wo,
    const float* __restrict__ out, int t)
{
    __shared__ float As[16][132];
    __shared__ float Bs[16][68];

    const int g = blockIdx.y;
    const int s = blockIdx.z;
    const float* __restrict__ W = (g==0)?Wf:(g==1)?Wi:(g==2)?Wu:Wo;
    const float* __restrict__ h = (t==0) ? g_zero : (out + (size_t)(t-1)*BH);
    const int n0  = blockIdx.x*64;
    const int k0  = s*512;
    const int tid = threadIdx.x;
    const int tx  = tid & 7;     // n group (8 * 8 = 64)
    const int ty  = tid >> 3;    // m group (16 * 8 = 128)

    unsigned long long acc[8][4];
    #pragma unroll
    for (int i=0;i<8;i++){
        #pragma unroll
        for (int j=0;j<4;j++) acc[i][j]=0ull;
    }

    for (int kt=0; kt<512; kt+=16){
        #pragma unroll
        for (int i=0;i<4;i++){                      // A (h) tile: 128 rows x 16 k
            int f = tid + i*128;
            int row = f>>2, kq = f&3;
            float4 v = *(const float4*)(h + (size_t)row*HH + k0 + kt + kq*4);
            As[kq*4+0][row]=v.x; As[kq*4+1][row]=v.y; As[kq*4+2][row]=v.z; As[kq*4+3][row]=v.w;
        }
        #pragma unroll
        for (int i=0;i<2;i++){                      // B (W) tile: 64 rows x 16 k
            int f = tid + i*128;
            int row = f>>2, kq = f&3;
            float4 v = *(const float4*)(W + (size_t)(n0+row)*DH + 1024 + k0 + kt + kq*4);
            Bs[kq*4+0][row]=v.x; Bs[kq*4+1][row]=v.y; Bs[kq*4+2][row]=v.z; Bs[kq*4+3][row]=v.w;
        }
        __syncthreads();
        #pragma unroll
        for (int k=0;k<16;k++){
            float a[8];
            *(float4*)(a)   = *(const float4*)&As[k][ty*8];
            *(float4*)(a+4) = *(const float4*)&As[k][ty*8+4];
            ulonglong2 q0 = *(const ulonglong2*)&Bs[k][tx*8];
            ulonglong2 q1 = *(const ulonglong2*)&Bs[k][tx*8+4];
            unsigned long long b[4] = {q0.x, q0.y, q1.x, q1.y};
            #pragma unroll
            for (int im=0; im<8; im++){
                unsigned long long a2 = splat2(a[im]);
                #pragma unroll
                for (int in=0; in<4; in++) fma2(acc[im][in], a2, b[in]);
            }
        }
        __syncthreads();
    }

    float* __restrict__ Pb = g_P + (size_t)(s*4+g)*BH + n0 + tx*8;
    #pragma unroll
    for (int im=0; im<8; im++){
        int b = ty*8+im;
        float o8[8];
        #pragma unroll
        for (int in=0;in<4;in++){
            float2 p = unpack2(acc[im][in]);
            o8[in*2] = p.x; o8[in*2+1] = p.y;
        }
        *(float4*)(Pb + (size_t)b*HH)     = *(float4*)(o8);
        *(float4*)(Pb + (size_t)b*HH + 4) = *(float4*)(o8+4);
    }
}

// ---------------------------------------------------------------------------
// Elementwise step: RBF k, gates, cell/hidden update. One block per batch row.
// ---------------------------------------------------------------------------
__global__ __launch_bounds__(256) void k_step(
    const float* __restrict__ X, float* __restrict__ out, int t)
{
    const int b   = blockIdx.x;
    const int tid = threadIdx.x;
    const float* __restrict__ x  = X + ((size_t)t*BB + b)*DD;
    const float* __restrict__ hp = (t==0) ? (g_zero + (size_t)b*HH)
                                          : (out + (size_t)(t-1)*BH + (size_t)b*HH);
    __shared__ float red[256];
    float sacc = 0.f;
    #pragma unroll
    for (int j=0;j<4;j++){
        float d = x[tid + j*256] - hp[tid + j*256];
        sacc += d*d;
    }
    red[tid] = sacc; __syncthreads();
    #pragma unroll
    for (int w=128; w>0; w>>=1){
        if (tid < w) red[tid] += red[tid+w];
        __syncthreads();
    }
    const float kk = expf(-red[0]);   // GAMMA = 1 (underflows to 0 in practice, matching reference)

    const float* __restrict__ Zb = g_Z + (size_t)t*4*BH + (size_t)b*HH;   // Zb[g*BH + n]
    const float* __restrict__ P  = g_P + (size_t)b*HH;                    // P[(s*4+g)*BH + n]
    float* __restrict__ c  = g_c + (size_t)b*HH;
    float* __restrict__ ho = out + (size_t)t*BH + (size_t)b*HH;

    #pragma unroll
    for (int j=0;j<4;j++){
        int n = tid + j*256;
        float pf = Zb[0*BH + n] + P[0*BH + n] + P[4*BH + n] + kk;
        float pi = Zb[1*BH + n] + P[1*BH + n] + P[5*BH + n] + kk;
        float pu = Zb[2*BH + n] + P[2*BH + n] + P[6*BH + n];
        float po = Zb[3*BH + n] + P[3*BH + n] + P[7*BH + n] + kk;
        float f_ = 1.f/(1.f+expf(-pf));
        float i_ = 1.f/(1.f+expf(-pi));
        float u_ = tanhf(pu);
        float o_ = 1.f/(1.f+expf(-po));
        float cn = f_*c[n] + i_*u_;
        c[n]  = cn;
        ho[n] = o_*tanhf(cn);
    }
}

__global__ void k_fin(float* __restrict__ out){
    int i = blockIdx.x*blockDim.x + threadIdx.x;   // grid covers exactly BH
    out[(size_t)TT*BH + i]      = out[(size_t)(TT-1)*BH + i];   // hT = outs[T-1]
    out[(size_t)TT*BH + BH + i] = g_c[i];                        // cT
}

extern "C" void kernel_launch(void* const* d_in, const int* in_sizes, int n_in,
                              void* d_out, int out_size)
{
    const float* X   = (const float*)d_in[0];
    const float* Wf  = (const float*)d_in[1];
    const float* bfp = (const float*)d_in[2];
    const float* Wi  = (const float*)d_in[3];
    const float* bip = (const float*)d_in[4];
    const float* Wu  = (const float*)d_in[5];
    const float* bup = (const float*)d_in[6];
    const float* Wo  = (const float*)d_in[7];
    const float* bop = (const float*)d_in[8];
    float* out = (float*)d_out;

    k_init<<<BH/256, 256>>>();
    k_pre<<<dim3(8, 256, 4), 256>>>(X, Wf, Wi, Wu, Wo, bfp, bip, bup, bop);
    for (int t = 0; t < TT; t++){
        k_rec<<<dim3(16, 4, 2), 128>>>(Wf, Wi, Wu, Wo, out, t);
        k_step<<<BB, 256>>>(X, out, t);
    }
    k_fin<<<BH/256, 256>>>(out);
}

// round 3
// speedup vs baseline: 2.7927x; 2.7927x over previous
#include <cuda_runtime.h>
#include <cuda_bf16.h>
#include <math.h>
#include <stdint.h>

#define TT 256
#define BB 128
#define HH 1024
#define DD 1024
#define BH (BB*HH)
#define NG 4096       // 4 gates * 1024
#define KSPLIT 4

// ---------------- device global scratch (no allocs allowed) ----------------
static __device__ float g_Z[(size_t)TT*BB*NG];          // input-projection precompute
static __device__ float g_P[(size_t)KSPLIT*BB*NG];      // recurrent partials
static __device__ float g_c[BH];
static __device__ float g_zero[BH];
static __device__ float g_bias[NG];
static __device__ __align__(16) __nv_bfloat16 g_Xhi[(size_t)TT*BB*DD];
static __device__ __align__(16) __nv_bfloat16 g_Xlo[(size_t)TT*BB*DD];
static __device__ __align__(16) __nv_bfloat16 g_Wxhi[(size_t)NG*HH];
static __device__ __align__(16) __nv_bfloat16 g_Wxlo[(size_t)NG*HH];
static __device__ __align__(16) __nv_bfloat16 g_Whhi[(size_t)NG*HH];
static __device__ __align__(16) __nv_bfloat16 g_Whlo[(size_t)NG*HH];
static __device__ __align__(16) __nv_bfloat16 g_hhi[BH];
static __device__ __align__(16) __nv_bfloat16 g_hlo[BH];

// ---------------- PTX helpers (baseline ISA only: sm_80-compatible) --------
__device__ __forceinline__ uint32_t smem_u32(const void* p){
    uint32_t a;
    asm("{ .reg .u64 t; cvta.to.shared.u64 t, %1; cvt.u32.u64 %0, t; }" : "=r"(a) : "l"(p));
    return a;
}
__device__ __forceinline__ void ldsm4(uint32_t& r0, uint32_t& r1, uint32_t& r2, uint32_t& r3, uint32_t a){
    asm volatile("ldmatrix.sync.aligned.m8n8.x4.shared.b16 {%0,%1,%2,%3}, [%4];"
                 : "=r"(r0), "=r"(r1), "=r"(r2), "=r"(r3) : "r"(a));
}
__device__ __forceinline__ void mma16816(float* d, const uint32_t* a, const uint32_t* b){
    asm volatile("mma.sync.aligned.m16n8k16.row.col.f32.bf16.bf16.f32 "
                 "{%0,%1,%2,%3}, {%4,%5,%6,%7}, {%8,%9}, {%0,%1,%2,%3};"
                 : "+f"(d[0]), "+f"(d[1]), "+f"(d[2]), "+f"(d[3])
                 : "r"(a[0]), "r"(a[1]), "r"(a[2]), "r"(a[3]), "r"(b[0]), "r"(b[1]));
}
__device__ __forceinline__ void cpa16(uint32_t dst, const void* src){
    asm volatile("cp.async.cg.shared.global [%0], [%1], 16;" :: "r"(dst), "l"(src));
}
#define CP_COMMIT asm volatile("cp.async.commit_group;" ::: "memory")
#define CP_WAIT1  asm volatile("cp.async.wait_group 1;" ::: "memory")
#define CP_WAIT0  asm volatile("cp.async.wait_group 0;" ::: "memory")

// ---------------- init ----------------
__global__ void k_init(const float* __restrict__ bf, const float* __restrict__ bi,
                       const float* __restrict__ bu, const float* __restrict__ bo){
    int i = blockIdx.x*256 + threadIdx.x;   // grid covers BH
    g_c[i] = 0.f; g_zero[i] = 0.f;
    g_hhi[i] = __float2bfloat16(0.f);
    g_hlo[i] = __float2bfloat16(0.f);
    if (i < NG){
        int g = i >> 10, n = i & 1023;
        g_bias[i] = (g==0?bf:g==1?bi:g==2?bu:bo)[n];
    }
}

// ---------------- fp32 -> bf16 hi/lo split ----------------
__device__ __forceinline__ void split4(float4 a, uint2& hi, uint2& lo){
    union { __nv_bfloat16 b[4]; uint2 u; } H, L;
    float x[4] = {a.x, a.y, a.z, a.w};
    #pragma unroll
    for (int j=0;j<4;j++){
        __nv_bfloat16 h = __float2bfloat16(x[j]);
        H.b[j] = h;
        L.b[j] = __float2bfloat16(x[j] - __bfloat162float(h));
    }
    hi = H.u; lo = L.u;
}

__global__ __launch_bounds__(256) void k_cvtX(const float* __restrict__ X){
    size_t v = (size_t)blockIdx.x*256 + threadIdx.x;
    float4 a = *(const float4*)(X + v*4);
    uint2 hi, lo; split4(a, hi, lo);
    *(uint2*)((char*)g_Xhi + v*8) = hi;
    *(uint2*)((char*)g_Xlo + v*8) = lo;
}

__global__ __launch_bounds__(256) void k_cvtW(const float* __restrict__ Wf, const float* __restrict__ Wi,
                                              const float* __restrict__ Wu, const float* __restrict__ Wo){
    int g = blockIdx.y;
    const float* __restrict__ W = (g==0)?Wf:(g==1)?Wi:(g==2)?Wu:Wo;
    int v = blockIdx.x*256 + threadIdx.x;
    int n  = v >> 8;
    int kv = (v & 255) * 4;
    size_t o = ((size_t)g*1024 + n)*1024 + kv;
    float4 ax = *(const float4*)(W + (size_t)n*2048 + kv);
    float4 ah = *(const float4*)(W + (size_t)n*2048 + 1024 + kv);
    uint2 hi, lo;
    split4(ax, hi, lo);
    *(uint2*)((char*)g_Wxhi + o*2) = hi;
    *(uint2*)((char*)g_Wxlo + o*2) = lo;
    split4(ah, hi, lo);
    *(uint2*)((char*)g_Whhi + o*2) = hi;
    *(uint2*)((char*)g_Whlo + o*2) = lo;
}

// ---------------- bf16x3 HMMA GEMM: 128x128 tile, BK=32, double-buffered ----
// Smem stage (32KB): Ah[128][32] +0 | Al +8KB | Bh +16KB | Bl +24KB. Two stages.
// Swizzle: 16B chunk c (0..3) of row r stored at chunk c ^ ((r>>1)&3).
template<int MODE>
__global__ __launch_bounds__(256) void k_mma(){
    extern __shared__ char smem[];
    const uint32_t sbase = smem_u32(smem);
    const int tid  = threadIdx.x;
    const int lane = tid & 31;
    const int wid  = tid >> 5;
    const int wm   = wid >> 1;     // 0..3
    const int wn   = wid & 1;      // 0..1
    const int n0   = blockIdx.x * 128;
    const int y    = blockIdx.y;

    const __nv_bfloat16 *Ah, *Al, *Bh, *Bl;
    float* out;
    int NS;
    if (MODE == 0){
        Ah = g_Xhi + (size_t)y*131072;  Al = g_Xlo + (size_t)y*131072;
        Bh = g_Wxhi + (size_t)n0*1024;  Bl = g_Wxlo + (size_t)n0*1024;
        out = g_Z + (size_t)y*BB*NG;    NS = 32;
    } else {
        Ah = g_hhi + y*256;             Al = g_hlo + y*256;
        Bh = g_Whhi + (size_t)n0*1024 + y*256;
        Bl = g_Whlo + (size_t)n0*1024 + y*256;
        out = g_P + (size_t)y*BB*NG;    NS = 8;
    }

    float acc[2][8][4];
    #pragma unroll
    for (int i=0;i<2;i++)
        #pragma unroll
        for (int j=0;j<8;j++)
            #pragma unroll
            for (int q=0;q<4;q++) acc[i][j][q] = 0.f;

    // per-thread load geometry
    int lrow[2], ldst[2], lgc[2];
    #pragma unroll
    for (int i=0;i<2;i++){
        int ch = tid + i*256;
        int r = ch >> 2, c = ch & 3;
        lrow[i] = r; lgc[i] = c*8;
        ldst[i] = r*64 + ((c ^ ((r>>1)&3))<<4);
    }

    #define LOAD_SLAB(stg, ks) do {                                   \
        uint32_t sb_ = sbase + (stg)*32768;                            \
        _Pragma("unroll")                                              \
        for (int i_=0;i_<2;i_++){                                      \
            size_t go_ = (size_t)lrow[i_]*1024 + (ks) + lgc[i_];       \
            cpa16(sb_ + ldst[i_],          Ah + go_);                  \
            cpa16(sb_ + 8192  + ldst[i_],  Al + go_);                  \
            cpa16(sb_ + 16384 + ldst[i_],  Bh + go_);                  \
            cpa16(sb_ + 24576 + ldst[i_],  Bl + go_);                  \
        }                                                              \
    } while(0)

    LOAD_SLAB(0, 0);
    CP_COMMIT;

    for (int s = 0; s < NS; s++){
        if (s+1 < NS){ LOAD_SLAB((s+1)&1, (s+1)*32); CP_COMMIT; CP_WAIT1; }
        else CP_WAIT0;
        __syncthreads();

        const uint32_t sA = sbase + (s&1)*32768;
        const uint32_t sB = sA + 16384;
        #pragma unroll
        for (int kk = 0; kk < 2; kk++){
            uint32_t ah[2][4], al[2][4];
            #pragma unroll
            for (int mt=0; mt<2; mt++){
                int r = wm*32 + mt*16 + (lane & 15);
                int c = kk*2 + (lane >> 4);
                uint32_t ad = sA + r*64 + (((c ^ ((r>>1)&3)))<<4);
                ldsm4(ah[mt][0], ah[mt][1], ah[mt][2], ah[mt][3], ad);
                ldsm4(al[mt][0], al[mt][1], al[mt][2], al[mt][3], ad + 8192);
            }
            #pragma unroll
            for (int ntp=0; ntp<4; ntp++){
                int q = lane >> 3;
                int n = wn*64 + ntp*16 + ((q>>1)<<3) + (lane & 7);
                int kc = kk*2 + (q & 1);
                uint32_t bd = sB + n*64 + (((kc ^ ((n>>1)&3)))<<4);
                uint32_t bh[4], bl[4];
                ldsm4(bh[0], bh[1], bh[2], bh[3], bd);
                ldsm4(bl[0], bl[1], bl[2], bl[3], bd + 8192);
                #pragma unroll
                for (int mt=0; mt<2; mt++){
                    mma16816(acc[mt][2*ntp],   ah[mt], bh);
                    mma16816(acc[mt][2*ntp],   ah[mt], bl);
                    mma16816(acc[mt][2*ntp],   al[mt], bh);
                    mma16816(acc[mt][2*ntp+1], ah[mt], bh+2);
                    mma16816(acc[mt][2*ntp+1], ah[mt], bl+2);
                    mma16816(acc[mt][2*ntp+1], al[mt], bh+2);
                }
            }
        }
        __syncthreads();
    }

    // epilogue: acc -> out (+bias for MODE 0)
    #pragma unroll
    for (int mt=0; mt<2; mt++){
        int m = wm*32 + mt*16 + (lane >> 2);
        #pragma unroll
        for (int nt=0; nt<8; nt++){
            int nc = n0 + wn*64 + nt*8 + (lane & 3)*2;
            float b0 = 0.f, b1 = 0.f;
            if (MODE == 0){ b0 = g_bias[nc]; b1 = g_bias[nc+1]; }
            float2 v0 = make_float2(acc[mt][nt][0] + b0, acc[mt][nt][1] + b1);
            float2 v1 = make_float2(acc[mt][nt][2] + b0, acc[mt][nt][3] + b1);
            *(float2*)(out + (size_t)m*NG + nc)     = v0;
            *(float2*)(out + (size_t)(m+8)*NG + nc) = v1;
        }
    }
}

// ---------------- elementwise LSTM step ----------------
__global__ __launch_bounds__(256) void k_step(const float* __restrict__ X,
                                              float* __restrict__ out, int t){
    const int b   = blockIdx.x;
    const int q   = blockIdx.y;
    const int tid = threadIdx.x;
    const float* __restrict__ x  = X + ((size_t)t*BB + b)*DD;
    const float* __restrict__ hp = t ? out + ((size_t)(t-1)*BB + b)*HH
                                     : g_zero + (size_t)b*HH;
    float s = 0.f;
    #pragma unroll
    for (int j=0;j<4;j++){
        float d = x[tid + j*256] - hp[tid + j*256];
        s += d*d;
    }
    #pragma unroll
    for (int o=16;o;o>>=1) s += __shfl_xor_sync(0xFFFFFFFFu, s, o);
    __shared__ float red[8];
    if ((tid & 31) == 0) red[tid >> 5] = s;
    __syncthreads();
    float tot = red[0]+red[1]+red[2]+red[3]+red[4]+red[5]+red[6]+red[7];
    const float kk = expf(-tot);

    const int n = q*256 + tid;
    const float* __restrict__ Z = g_Z + ((size_t)t*BB + b)*NG;
    float pf = Z[n] + kk, pi = Z[1024+n] + kk, pu = Z[2048+n], po = Z[3072+n] + kk;
    #pragma unroll
    for (int sp=0; sp<KSPLIT; sp++){
        const float* __restrict__ P = g_P + ((size_t)sp*BB + b)*NG;
        pf += P[n]; pi += P[1024+n]; pu += P[2048+n]; po += P[3072+n];
    }
    float f_ = 1.f/(1.f + expf(-pf));
    float i_ = 1.f/(1.f + expf(-pi));
    float u_ = tanhf(pu);
    float o_ = 1.f/(1.f + expf(-po));
    const int ci = b*HH + n;
    float cn = f_*g_c[ci] + i_*u_;
    g_c[ci] = cn;
    float h = o_*tanhf(cn);
    out[((size_t)t*BB + b)*HH + n] = h;
    __nv_bfloat16 hh = __float2bfloat16(h);
    g_hhi[ci] = hh;
    g_hlo[ci] = __float2bfloat16(h - __bfloat162float(hh));
}

__global__ void k_fin(float* __restrict__ out){
    int i = blockIdx.x*256 + threadIdx.x;
    out[(size_t)TT*BH + i]      = out[(size_t)(TT-1)*BH + i];
    out[(size_t)TT*BH + BH + i] = g_c[i];
}

// ---------------- launch ----------------
#define SMEM_BYTES 65536

extern "C" void kernel_launch(void* const* d_in, const int* in_sizes, int n_in,
                              void* d_out, int out_size)
{
    const float* X   = (const float*)d_in[0];
    const float* Wf  = (const float*)d_in[1];
    const float* bfp = (const float*)d_in[2];
    const float* Wi  = (const float*)d_in[3];
    const float* bip = (const float*)d_in[4];
    const float* Wu  = (const float*)d_in[5];
    const float* bup = (const float*)d_in[6];
    const float* Wo  = (const float*)d_in[7];
    const float* bop = (const float*)d_in[8];
    float* out = (float*)d_out;

    cudaFuncSetAttribute(k_mma<0>, cudaFuncAttributeMaxDynamicSharedMemorySize, SMEM_BYTES);
    cudaFuncSetAttribute(k_mma<1>, cudaFuncAttributeMaxDynamicSharedMemorySize, SMEM_BYTES);

    k_init<<<BH/256, 256>>>(bfp, bip, bup, bop);
    k_cvtX<<<32768, 256>>>(X);
    k_cvtW<<<dim3(1024, 4), 256>>>(Wf, Wi, Wu, Wo);
    k_mma<0><<<dim3(32, 256), 256, SMEM_BYTES>>>();       // precompute Z
    for (int t = 0; t < TT; t++){
        k_mma<1><<<dim3(32, KSPLIT), 256, SMEM_BYTES>>>();  // recurrent partials
        k_step<<<dim3(BB, 4), 256>>>(X, out, t);
    }
    k_fin<<<BH/256, 256>>>(out);
}